// round 14
// baseline (speedup 1.0000x reference)
#include <cuda_runtime.h>
#include <math.h>

// Problem constants
#define S_N   256
#define V_N   200
#define F_N   5
#define G_N   80
#define NT    16
#define NR    5
#define NROT  16
#define EPSF  1e-5f

#define TWO_PI_F 6.28318530717958647692f
#define DTH_F    0.39269908169872415481f
#define LOG2E_F  1.44269504088896340736f

typedef unsigned long long ull;

// Scratch
__device__ float d_DESC[(size_t)S_N * 400];    // [s][f*80+gp], post max+bias+relu
__device__ int   d_CTR;                        // k45 completion counter

// ---------------- packed f32x2 helpers ----------------
__device__ __forceinline__ ull ffma2(ull a, ull b, ull c) {
    ull d;
    asm("fma.rn.f32x2 %0, %1, %2, %3;" : "=l"(d) : "l"(a), "l"(b), "l"(c));
    return d;
}
__device__ __forceinline__ ull addf2(ull a, ull b) {
    ull d;
    asm("add.rn.f32x2 %0, %1, %2;" : "=l"(d) : "l"(a), "l"(b));
    return d;
}
__device__ __forceinline__ ull pack2(float x) {
    ull d;
    asm("mov.b64 %0, {%1, %1};" : "=l"(d) : "f"(x));
    return d;
}
__device__ __forceinline__ ull pack2f(float a, float b) {
    ull d;
    asm("mov.b64 %0, {%1, %2};" : "=l"(d) : "f"(a), "f"(b));
    return d;
}
__device__ __forceinline__ float2 unpack2(ull v) {
    float2 f;
    asm("mov.b64 {%0, %1}, %2;" : "=f"(f.x), "=f"(f.y) : "l"(v));
    return f;
}
__device__ __forceinline__ float ex2f(float x) {
    float r;
    asm("ex2.approx.f32 %0, %1;" : "=f"(r) : "f"(x));
    return r;
}

// ---------------------------------------------------------------------------
// k123 (fused gaussian-GEMM + conv + max + bias + relu): one block per s,
// 256 threads = (v-half 0/1) x (r2 0..7, k 0..15).
// Phase 1: 2-rotation FFMA2 GEMM over the half's 100 v — 15 useful pairs
//          per rotation (the 16th pair was zero padding; dropped).
// Phase 2: combine halves via smem, normalize, GDN -> SMEM [g][f][rp][2].
// Phase 3: conv GEMM vs W, max over 16 rotations, bias + relu -> d_DESC.
// ---------------------------------------------------------------------------
__global__ __launch_bounds__(256, 2)
void k123(const float* __restrict__ feat,
          const float* __restrict__ rho,
          const float* __restrict__ theta,
          const float* __restrict__ mask,
          const float* __restrict__ mu_rho,
          const float* __restrict__ sigma_rho,
          const float* __restrict__ mu_theta,
          const float* __restrict__ sigma_theta,
          const float* __restrict__ Wc,
          const float* __restrict__ bc)
{
    __shared__ float As[(V_N + 2) * 32];   // 25.9 KB; later reused: cbuf / gdn
    __shared__ float t_s[V_N];
    __shared__ float Wsh[G_N * G_N];       // 25.6 KB

    int s   = blockIdx.x;
    int tid = threadIdx.x;
    int vh  = tid >> 7;                    // v half
    int l   = tid & 127;
    int r2  = l >> 4;                      // 0..7
    int k   = l & 15;

    if (s == 0 && tid == 0) d_CTR = 0;     // reset k45 counter (stream-ordered)

    // theta-gaussian constants (one k, two rotations)
    float mu_k  = __ldg(&mu_theta[k]);
    float st    = __ldg(&sigma_theta[k]);
    float sL    = sqrtf(LOG2E_F / (st * st + EPSF));
    float rdelA = (float)r2 * DTH_F;
    float rdelB = (float)(r2 + 8) * DTH_F;
    float c0    = -mu_k * sL;
    float c1    = -(TWO_PI_F + mu_k) * sL;

    // ---- stage W (all threads) ----
    {
        const float4* wsrc = (const float4*)Wc;
        float4* wdst = (float4*)Wsh;
        for (int i = tid; i < 1600; i += 256) wdst[i] = wsrc[i];
    }

    // ---- stage A, all 200 rows (float4 stores) ----
    if (tid < V_N) {
        int v   = tid;
        int idx = s * V_N + v;
        float rhv = rho[idx];
        float m   = mask[idx];
        t_s[v]    = theta[idx];
        float fv[5];
#pragma unroll
        for (int f = 0; f < 5; f++) fv[f] = feat[idx * 5 + f];
        float ar[32];
#pragma unroll
        for (int p = 0; p < NR; p++) {
            float mr = __ldg(&mu_rho[p * 16]);
            float sr = __ldg(&sigma_rho[p * 16]);
            float d  = rhv - mr;
            float rg = ex2f(-(d * d) * (LOG2E_F / (sr * sr + EPSF)));
            float rm = rg * m;
            ar[p * 6] = rm;
#pragma unroll
            for (int f = 0; f < 5; f++) ar[p * 6 + 1 + f] = rm * fv[f];
        }
        ar[30] = 0.0f; ar[31] = 0.0f;
        float4* dst = (float4*)(As + v * 32);
#pragma unroll
        for (int j4 = 0; j4 < 8; j4++) dst[j4] = ((const float4*)ar)[j4];
    } else if (tid < V_N + 16) {
        ((float4*)(As + V_N * 32))[tid - V_N] = make_float4(0.f, 0.f, 0.f, 0.f);
    }
    __syncthreads();

    // ---- phase 1: 100 v of this half, 2 rotations x 15 pairs per thread ----
    ull accA[15], accB[15];
#pragma unroll
    for (int j = 0; j < 15; j++) { accA[j] = 0ull; accB[j] = 0ull; }

    const int vbase = vh * 100;
    ulonglong2 qA[4], qB[4];
    {
        const ulonglong2* row0 = (const ulonglong2*)(As + vbase * 32);
#pragma unroll
        for (int j = 0; j < 4; j++) qA[j] = row0[j];
    }

#define K12_STEP(VV, CUR, NXT)                                                \
    {                                                                         \
        const ulonglong2* rn = (const ulonglong2*)(As + ((VV) + 1) * 32);     \
        _Pragma("unroll")                                                     \
        for (int j = 0; j < 4; j++) NXT[j] = rn[j];                           \
        float tv  = t_s[VV];                                                  \
        float trA = tv + rdelA;                                               \
        float cA  = (trA >= TWO_PI_F) ? c1 : c0;                              \
        float xA  = fmaf(trA, sL, cA);                                        \
        ull tgA   = pack2(ex2f(-xA * xA));                                    \
        float trB = tv + rdelB;                                               \
        float cB  = (trB >= TWO_PI_F) ? c1 : c0;                              \
        float xB  = fmaf(trB, sL, cB);                                        \
        ull tgB   = pack2(ex2f(-xB * xB));                                    \
        _Pragma("unroll")                                                     \
        for (int j = 0; j < 4; j++) {                                         \
            accA[2 * j + 0] = ffma2(tgA, CUR[j].x, accA[2 * j + 0]);          \
            accA[2 * j + 1] = ffma2(tgA, CUR[j].y, accA[2 * j + 1]);          \
            accB[2 * j + 0] = ffma2(tgB, CUR[j].x, accB[2 * j + 0]);          \
            accB[2 * j + 1] = ffma2(tgB, CUR[j].y, accB[2 * j + 1]);          \
        }                                                                     \
        const ulonglong2* rv = (const ulonglong2*)(As + (VV) * 32 + 16);      \
        ulonglong2 q4 = rv[0], q5 = rv[1], q6 = rv[2];                        \
        ull q7 = *(const ull*)(As + (VV) * 32 + 28);                          \
        accA[8]  = ffma2(tgA, q4.x, accA[8]);                                 \
        accA[9]  = ffma2(tgA, q4.y, accA[9]);                                 \
        accA[10] = ffma2(tgA, q5.x, accA[10]);                                \
        accA[11] = ffma2(tgA, q5.y, accA[11]);                                \
        accA[12] = ffma2(tgA, q6.x, accA[12]);                                \
        accA[13] = ffma2(tgA, q6.y, accA[13]);                                \
        accA[14] = ffma2(tgA, q7,   accA[14]);                                \
        accB[8]  = ffma2(tgB, q4.x, accB[8]);                                 \
        accB[9]  = ffma2(tgB, q4.y, accB[9]);                                 \
        accB[10] = ffma2(tgB, q5.x, accB[10]);                                \
        accB[11] = ffma2(tgB, q5.y, accB[11]);                                \
        accB[12] = ffma2(tgB, q6.x, accB[12]);                                \
        accB[13] = ffma2(tgB, q6.y, accB[13]);                                \
        accB[14] = ffma2(tgB, q7,   accB[14]);                                \
    }

#pragma unroll 2
    for (int vo = 0; vo < 100; vo += 2) {
        int v = vbase + vo;
        K12_STEP(v,     qA, qB)
        K12_STEP(v + 1, qB, qA)
    }
#undef K12_STEP

    // ---- phase 2: combine halves via smem (cbuf in As region) ----
    ull* cbuf = (ull*)As;   // 15 * 128 ull
    __syncthreads();        // done reading As/t_s
    if (vh == 1) {
#pragma unroll
        for (int j = 0; j < 15; j++) cbuf[j * 128 + l] = accA[j];
    }
    __syncthreads();
    if (vh == 0) {
#pragma unroll
        for (int j = 0; j < 15; j++) accA[j] = addf2(accA[j], cbuf[j * 128 + l]);
    }
    __syncthreads();
    if (vh == 1) {
#pragma unroll
        for (int j = 0; j < 15; j++) cbuf[j * 128 + l] = accB[j];
    }
    __syncthreads();
    if (vh == 0) {
#pragma unroll
        for (int j = 0; j < 15; j++) accB[j] = addf2(accB[j], cbuf[j * 128 + l]);
    }
    __syncthreads();   // all cbuf reads done before gdn overwrites the region

    // ---- normalize + write GDN to SMEM [g][f][rp][2] (vh0 threads) ----
    ull* gdn = (ull*)As;   // 3200 ull = 25.6 KB (fits As)
    if (vh == 0) {
#pragma unroll
        for (int p = 0; p < NR; p++) {
            float2 a0 = unpack2(accA[p * 3 + 0]);
            float2 a1 = unpack2(accA[p * 3 + 1]);
            float2 a2 = unpack2(accA[p * 3 + 2]);
            float2 b0 = unpack2(accB[p * 3 + 0]);
            float2 b1 = unpack2(accB[p * 3 + 1]);
            float2 b2 = unpack2(accB[p * 3 + 2]);
            float invA = 1.0f / (a0.x + EPSF);
            float invB = 1.0f / (b0.x + EPSF);
            int g = p * 16 + k;
            ull* gb = gdn + ((size_t)g * 5) * 8 + r2;
            gb[0 * 8] = pack2f(a0.y * invA, b0.y * invB);   // f0
            gb[1 * 8] = pack2f(a1.x * invA, b1.x * invB);   // f1
            gb[2 * 8] = pack2f(a1.y * invA, b1.y * invB);   // f2
            gb[3 * 8] = pack2f(a2.x * invA, b2.x * invB);   // f3
            gb[4 * 8] = pack2f(a2.y * invA, b2.y * invB);   // f4
        }
    }
    __syncthreads();

    // ---- phase 3: conv + max + bias + relu. 256 threads cover 400 cells:
    // cell0 = tid, cell1 = tid + 256 (if tid < 144).
    {
        int f0 = tid / 80, gp0 = tid % 80;
        int c1i = tid + 256;
        int f1 = c1i / 80, gp1 = c1i % 80;
        bool has1 = (tid < 144);

        ull acc0[8], acc1[8];
#pragma unroll
        for (int j = 0; j < 8; j++) { acc0[j] = 0ull; acc1[j] = 0ull; }

#pragma unroll 4
        for (int g = 0; g < G_N; g++) {
            ull w0 = pack2(Wsh[g * 80 + gp0]);
            const ulonglong2* rp0 = (const ulonglong2*)(gdn + ((size_t)g * 5 + f0) * 8);
            ulonglong2 q0 = rp0[0], q1 = rp0[1], q2 = rp0[2], q3 = rp0[3];
            acc0[0] = ffma2(w0, q0.x, acc0[0]);
            acc0[1] = ffma2(w0, q0.y, acc0[1]);
            acc0[2] = ffma2(w0, q1.x, acc0[2]);
            acc0[3] = ffma2(w0, q1.y, acc0[3]);
            acc0[4] = ffma2(w0, q2.x, acc0[4]);
            acc0[5] = ffma2(w0, q2.y, acc0[5]);
            acc0[6] = ffma2(w0, q3.x, acc0[6]);
            acc0[7] = ffma2(w0, q3.y, acc0[7]);
            if (has1) {
                ull w1 = pack2(Wsh[g * 80 + gp1]);
                const ulonglong2* rp1 = (const ulonglong2*)(gdn + ((size_t)g * 5 + f1) * 8);
                ulonglong2 p0 = rp1[0], p1 = rp1[1], p2 = rp1[2], p3 = rp1[3];
                acc1[0] = ffma2(w1, p0.x, acc1[0]);
                acc1[1] = ffma2(w1, p0.y, acc1[1]);
                acc1[2] = ffma2(w1, p1.x, acc1[2]);
                acc1[3] = ffma2(w1, p1.y, acc1[3]);
                acc1[4] = ffma2(w1, p2.x, acc1[4]);
                acc1[5] = ffma2(w1, p2.y, acc1[5]);
                acc1[6] = ffma2(w1, p3.x, acc1[6]);
                acc1[7] = ffma2(w1, p3.y, acc1[7]);
            }
        }

        float mx0 = -1e30f;
#pragma unroll
        for (int j = 0; j < 8; j++) {
            float2 q = unpack2(acc0[j]);
            mx0 = fmaxf(mx0, fmaxf(q.x, q.y));
        }
        d_DESC[(size_t)s * 400 + tid] = fmaxf(mx0 + bc[tid], 0.0f);

        if (has1) {
            float mx1 = -1e30f;
#pragma unroll
            for (int j = 0; j < 8; j++) {
                float2 q = unpack2(acc1[j]);
                mx1 = fmaxf(mx1, fmaxf(q.x, q.y));
            }
            d_DESC[(size_t)s * 400 + c1i] = fmaxf(mx1 + bc[c1i], 0.0f);
        }
    }
}

// ---------------------------------------------------------------------------
// k45: grid 64, block 320 = (s_local 0..3, g 0..79). fcc with fw staged via
// smem chunks; the LAST block (atomic counter) computes score + loss.
// out: [0:20480) global_desc, [20480] data_loss, [20481:20609) score
// ---------------------------------------------------------------------------
__global__ __launch_bounds__(320) void k45_fcc_loss(const float* __restrict__ fw,
                                                    const float* __restrict__ fb,
                                                    float* __restrict__ out)
{
    __shared__ float fwsh[100 * 80];   // 32 KB chunk
    __shared__ float dsh[4 * 400];
    __shared__ float stats[4];
    __shared__ int   isLast;

    int tid = threadIdx.x;
    int sl  = tid / 80;
    int g   = tid % 80;
    int sb  = blockIdx.x * 4;

    {
        const float4* src = (const float4*)(d_DESC + (size_t)sb * 400);
        float4* dst = (float4*)dsh;
        for (int i = tid; i < 400; i += 320) dst[i] = src[i];
    }

    float acc = 0.0f;
#pragma unroll
    for (int c = 0; c < 4; c++) {
        __syncthreads();
        const float4* src = (const float4*)(fw + (size_t)c * 100 * 80);
        float4* dst = (float4*)fwsh;
        for (int i = tid; i < 2000; i += 320) dst[i] = src[i];
        __syncthreads();

        const float* dr = &dsh[sl * 400 + c * 100];
#pragma unroll 5
        for (int j = 0; j < 100; j++)
            acc = fmaf(dr[j], fwsh[j * 80 + g], acc);
    }

    out[(size_t)(sb + sl) * 80 + g] = fb[g] + acc;

    // ---- completion counter; last block computes the loss ----
    __threadfence();
    if (tid == 0) isLast = (atomicAdd(&d_CTR, 1) == 63);
    __syncthreads();
    if (!isLast) return;
    __threadfence();   // acquire side: see all blocks' out writes

    float* sdist = dsh;   // reuse
    int w    = tid >> 5;  // 10 warps
    int lane = tid & 31;
    const float* gd = out;

    for (int p = w; p < 128; p += 10) {
        int il = p & 63;
        const float *xa, *xb;
        if (p < 64) { xa = gd + (size_t)(64 + il) * 80;  xb = gd + (size_t)il * 80; }
        else        { xa = gd + (size_t)(128 + il) * 80; xb = gd + (size_t)(192 + il) * 80; }
        float sum = 0.0f;
        if (lane < 20) {
            float4 a4 = ((const float4*)xa)[lane];
            float4 b4 = ((const float4*)xb)[lane];
            float dx = a4.x - b4.x, dy = a4.y - b4.y;
            float dz = a4.z - b4.z, dw = a4.w - b4.w;
            sum = dx * dx + dy * dy + dz * dz + dw * dw;
        }
#pragma unroll
        for (int off = 16; off; off >>= 1)
            sum += __shfl_xor_sync(0xffffffffu, sum, off);
        if (lane == 0) { sdist[p] = sum; out[20481 + p] = sum; }
    }
    __syncthreads();

    if (w == 0) {
        float v1 = fmaxf(sdist[lane], 0.0f);
        float v2 = fmaxf(sdist[lane + 32], 0.0f);
        float sum = v1 + v2;
#pragma unroll
        for (int off = 16; off; off >>= 1)
            sum += __shfl_xor_sync(0xffffffffu, sum, off);
        float m = sum * (1.0f / 64.0f);
        float q = (v1 - m) * (v1 - m) + (v2 - m) * (v2 - m);
#pragma unroll
        for (int off = 16; off; off >>= 1)
            q += __shfl_xor_sync(0xffffffffu, q, off);
        if (lane == 0) { stats[0] = m; stats[1] = q; }
    } else if (w == 1) {
        float v1 = fmaxf(10.0f - sdist[64 + lane], 0.0f);
        float v2 = fmaxf(10.0f - sdist[96 + lane], 0.0f);
        float sum = v1 + v2;
#pragma unroll
        for (int off = 16; off; off >>= 1)
            sum += __shfl_xor_sync(0xffffffffu, sum, off);
        float m = sum * (1.0f / 64.0f);
        float q = (v1 - m) * (v1 - m) + (v2 - m) * (v2 - m);
#pragma unroll
        for (int off = 16; off; off >>= 1)
            q += __shfl_xor_sync(0xffffffffu, q, off);
        if (lane == 0) { stats[2] = m; stats[3] = q; }
    }
    __syncthreads();

    if (tid == 0)
        out[20480] = sqrtf(stats[1] / 63.0f) + sqrtf(stats[3] / 63.0f)
                   + stats[0] + stats[2];
}

// ---------------------------------------------------------------------------
extern "C" void kernel_launch(void* const* d_in, const int* in_sizes, int n_in,
                              void* d_out, int out_size)
{
    const float* input_feat  = (const float*)d_in[0];
    const float* rho_coords  = (const float*)d_in[1];
    const float* theta_coord = (const float*)d_in[2];
    const float* mask        = (const float*)d_in[3];
    const float* mu_rho      = (const float*)d_in[4];
    const float* sigma_rho   = (const float*)d_in[5];
    const float* mu_theta    = (const float*)d_in[6];
    const float* sigma_theta = (const float*)d_in[7];
    const float* W_conv      = (const float*)d_in[8];
    const float* b_conv      = (const float*)d_in[9];
    const float* fcc_w       = (const float*)d_in[10];
    const float* fcc_b       = (const float*)d_in[11];
    float* out = (float*)d_out;

    k123<<<S_N, 256>>>(input_feat, rho_coords, theta_coord, mask,
                       mu_rho, sigma_rho, mu_theta, sigma_theta,
                       W_conv, b_conv);
    k45_fcc_loss<<<S_N / 4, 320>>>(fcc_w, fcc_b, out);
}

// round 15
// speedup vs baseline: 1.0697x; 1.0697x over previous
#include <cuda_runtime.h>
#include <math.h>

// Problem constants
#define S_N   256
#define V_N   200
#define F_N   5
#define G_N   80
#define NT    16
#define NR    5
#define NROT  16
#define EPSF  1e-5f

#define TWO_PI_F 6.28318530717958647692f
#define DTH_F    0.39269908169872415481f
#define LOG2E_F  1.44269504088896340736f

typedef unsigned long long ull;

// Scratch
__device__ float d_DESC[(size_t)S_N * 400];    // [s][f*80+gp], post max+bias+relu

// ---------------- packed f32x2 helpers ----------------
__device__ __forceinline__ ull ffma2(ull a, ull b, ull c) {
    ull d;
    asm("fma.rn.f32x2 %0, %1, %2, %3;" : "=l"(d) : "l"(a), "l"(b), "l"(c));
    return d;
}
__device__ __forceinline__ ull addf2(ull a, ull b) {
    ull d;
    asm("add.rn.f32x2 %0, %1, %2;" : "=l"(d) : "l"(a), "l"(b));
    return d;
}
__device__ __forceinline__ ull pack2(float x) {
    ull d;
    asm("mov.b64 %0, {%1, %1};" : "=l"(d) : "f"(x));
    return d;
}
__device__ __forceinline__ ull pack2f(float a, float b) {
    ull d;
    asm("mov.b64 %0, {%1, %2};" : "=l"(d) : "f"(a), "f"(b));
    return d;
}
__device__ __forceinline__ float2 unpack2(ull v) {
    float2 f;
    asm("mov.b64 {%0, %1}, %2;" : "=f"(f.x), "=f"(f.y) : "l"(v));
    return f;
}
__device__ __forceinline__ float ex2f(float x) {
    float r;
    asm("ex2.approx.f32 %0, %1;" : "=f"(r) : "f"(x));
    return r;
}

// ---------------------------------------------------------------------------
// k123 (fused gaussian-GEMM + conv + max + bias + relu): one block per s,
// 256 threads = (v-half 0/1) x (r2 0..7, k 0..15).
// Phase 1: 2-rotation FFMA2 GEMM over the half's 100 v — 15 useful pairs
//          per rotation (zero pad pair dropped).
// Phase 2: combine halves via smem, normalize, GDN -> SMEM [g][f][rp][2].
// Phase 3: conv GEMM vs W, max over 16 rotations, bias + relu -> d_DESC.
// ---------------------------------------------------------------------------
__global__ __launch_bounds__(256, 2)
void k123(const float* __restrict__ feat,
          const float* __restrict__ rho,
          const float* __restrict__ theta,
          const float* __restrict__ mask,
          const float* __restrict__ mu_rho,
          const float* __restrict__ sigma_rho,
          const float* __restrict__ mu_theta,
          const float* __restrict__ sigma_theta,
          const float* __restrict__ Wc,
          const float* __restrict__ bc)
{
    __shared__ float As[(V_N + 2) * 32];   // 25.9 KB; later reused: cbuf / gdn
    __shared__ float t_s[V_N];
    __shared__ float Wsh[G_N * G_N];       // 25.6 KB

    int s   = blockIdx.x;
    int tid = threadIdx.x;
    int vh  = tid >> 7;                    // v half
    int l   = tid & 127;
    int r2  = l >> 4;                      // 0..7
    int k   = l & 15;

    // theta-gaussian constants (one k, two rotations)
    float mu_k  = __ldg(&mu_theta[k]);
    float st    = __ldg(&sigma_theta[k]);
    float sL    = sqrtf(LOG2E_F / (st * st + EPSF));
    float rdelA = (float)r2 * DTH_F;
    float rdelB = (float)(r2 + 8) * DTH_F;
    float c0    = -mu_k * sL;
    float c1    = -(TWO_PI_F + mu_k) * sL;

    // ---- stage W (all threads) ----
    {
        const float4* wsrc = (const float4*)Wc;
        float4* wdst = (float4*)Wsh;
        for (int i = tid; i < 1600; i += 256) wdst[i] = wsrc[i];
    }

    // ---- stage A, all 200 rows (float4 stores) ----
    if (tid < V_N) {
        int v   = tid;
        int idx = s * V_N + v;
        float rhv = rho[idx];
        float m   = mask[idx];
        t_s[v]    = theta[idx];
        float fv[5];
#pragma unroll
        for (int f = 0; f < 5; f++) fv[f] = feat[idx * 5 + f];
        float ar[32];
#pragma unroll
        for (int p = 0; p < NR; p++) {
            float mr = __ldg(&mu_rho[p * 16]);
            float sr = __ldg(&sigma_rho[p * 16]);
            float d  = rhv - mr;
            float rg = ex2f(-(d * d) * (LOG2E_F / (sr * sr + EPSF)));
            float rm = rg * m;
            ar[p * 6] = rm;
#pragma unroll
            for (int f = 0; f < 5; f++) ar[p * 6 + 1 + f] = rm * fv[f];
        }
        ar[30] = 0.0f; ar[31] = 0.0f;
        float4* dst = (float4*)(As + v * 32);
#pragma unroll
        for (int j4 = 0; j4 < 8; j4++) dst[j4] = ((const float4*)ar)[j4];
    } else if (tid < V_N + 16) {
        ((float4*)(As + V_N * 32))[tid - V_N] = make_float4(0.f, 0.f, 0.f, 0.f);
    }
    __syncthreads();

    // ---- phase 1: 100 v of this half, 2 rotations x 15 pairs per thread ----
    ull accA[15], accB[15];
#pragma unroll
    for (int j = 0; j < 15; j++) { accA[j] = 0ull; accB[j] = 0ull; }

    const int vbase = vh * 100;
    ulonglong2 qA[4], qB[4];
    {
        const ulonglong2* row0 = (const ulonglong2*)(As + vbase * 32);
#pragma unroll
        for (int j = 0; j < 4; j++) qA[j] = row0[j];
    }

#define K12_STEP(VV, CUR, NXT)                                                \
    {                                                                         \
        const ulonglong2* rn = (const ulonglong2*)(As + ((VV) + 1) * 32);     \
        _Pragma("unroll")                                                     \
        for (int j = 0; j < 4; j++) NXT[j] = rn[j];                           \
        float tv  = t_s[VV];                                                  \
        float trA = tv + rdelA;                                               \
        float cA  = (trA >= TWO_PI_F) ? c1 : c0;                              \
        float xA  = fmaf(trA, sL, cA);                                        \
        ull tgA   = pack2(ex2f(-xA * xA));                                    \
        float trB = tv + rdelB;                                               \
        float cB  = (trB >= TWO_PI_F) ? c1 : c0;                              \
        float xB  = fmaf(trB, sL, cB);                                        \
        ull tgB   = pack2(ex2f(-xB * xB));                                    \
        _Pragma("unroll")                                                     \
        for (int j = 0; j < 4; j++) {                                         \
            accA[2 * j + 0] = ffma2(tgA, CUR[j].x, accA[2 * j + 0]);          \
            accA[2 * j + 1] = ffma2(tgA, CUR[j].y, accA[2 * j + 1]);          \
            accB[2 * j + 0] = ffma2(tgB, CUR[j].x, accB[2 * j + 0]);          \
            accB[2 * j + 1] = ffma2(tgB, CUR[j].y, accB[2 * j + 1]);          \
        }                                                                     \
        const ulonglong2* rv = (const ulonglong2*)(As + (VV) * 32 + 16);      \
        ulonglong2 q4 = rv[0], q5 = rv[1], q6 = rv[2];                        \
        ull q7 = *(const ull*)(As + (VV) * 32 + 28);                          \
        accA[8]  = ffma2(tgA, q4.x, accA[8]);                                 \
        accA[9]  = ffma2(tgA, q4.y, accA[9]);                                 \
        accA[10] = ffma2(tgA, q5.x, accA[10]);                                \
        accA[11] = ffma2(tgA, q5.y, accA[11]);                                \
        accA[12] = ffma2(tgA, q6.x, accA[12]);                                \
        accA[13] = ffma2(tgA, q6.y, accA[13]);                                \
        accA[14] = ffma2(tgA, q7,   accA[14]);                                \
        accB[8]  = ffma2(tgB, q4.x, accB[8]);                                 \
        accB[9]  = ffma2(tgB, q4.y, accB[9]);                                 \
        accB[10] = ffma2(tgB, q5.x, accB[10]);                                \
        accB[11] = ffma2(tgB, q5.y, accB[11]);                                \
        accB[12] = ffma2(tgB, q6.x, accB[12]);                                \
        accB[13] = ffma2(tgB, q6.y, accB[13]);                                \
        accB[14] = ffma2(tgB, q7,   accB[14]);                                \
    }

#pragma unroll 2
    for (int vo = 0; vo < 100; vo += 2) {
        int v = vbase + vo;
        K12_STEP(v,     qA, qB)
        K12_STEP(v + 1, qB, qA)
    }
#undef K12_STEP

    // ---- phase 2: combine halves via smem (cbuf in As region) ----
    ull* cbuf = (ull*)As;   // 15 * 128 ull
    __syncthreads();        // done reading As/t_s
    if (vh == 1) {
#pragma unroll
        for (int j = 0; j < 15; j++) cbuf[j * 128 + l] = accA[j];
    }
    __syncthreads();
    if (vh == 0) {
#pragma unroll
        for (int j = 0; j < 15; j++) accA[j] = addf2(accA[j], cbuf[j * 128 + l]);
    }
    __syncthreads();
    if (vh == 1) {
#pragma unroll
        for (int j = 0; j < 15; j++) cbuf[j * 128 + l] = accB[j];
    }
    __syncthreads();
    if (vh == 0) {
#pragma unroll
        for (int j = 0; j < 15; j++) accB[j] = addf2(accB[j], cbuf[j * 128 + l]);
    }
    __syncthreads();   // all cbuf reads done before gdn overwrites the region

    // ---- normalize + write GDN to SMEM [g][f][rp][2] (vh0 threads) ----
    ull* gdn = (ull*)As;   // 3200 ull = 25.6 KB (fits As)
    if (vh == 0) {
#pragma unroll
        for (int p = 0; p < NR; p++) {
            float2 a0 = unpack2(accA[p * 3 + 0]);
            float2 a1 = unpack2(accA[p * 3 + 1]);
            float2 a2 = unpack2(accA[p * 3 + 2]);
            float2 b0 = unpack2(accB[p * 3 + 0]);
            float2 b1 = unpack2(accB[p * 3 + 1]);
            float2 b2 = unpack2(accB[p * 3 + 2]);
            float invA = 1.0f / (a0.x + EPSF);
            float invB = 1.0f / (b0.x + EPSF);
            int g = p * 16 + k;
            ull* gb = gdn + ((size_t)g * 5) * 8 + r2;
            gb[0 * 8] = pack2f(a0.y * invA, b0.y * invB);   // f0
            gb[1 * 8] = pack2f(a1.x * invA, b1.x * invB);   // f1
            gb[2 * 8] = pack2f(a1.y * invA, b1.y * invB);   // f2
            gb[3 * 8] = pack2f(a2.x * invA, b2.x * invB);   // f3
            gb[4 * 8] = pack2f(a2.y * invA, b2.y * invB);   // f4
        }
    }
    __syncthreads();

    // ---- phase 3: conv + max + bias + relu. 256 threads cover 400 cells:
    // cell0 = tid, cell1 = tid + 256 (if tid < 144).
    {
        int f0 = tid / 80, gp0 = tid % 80;
        int c1i = tid + 256;
        int f1 = c1i / 80, gp1 = c1i % 80;
        bool has1 = (tid < 144);

        ull acc0[8], acc1[8];
#pragma unroll
        for (int j = 0; j < 8; j++) { acc0[j] = 0ull; acc1[j] = 0ull; }

#pragma unroll 4
        for (int g = 0; g < G_N; g++) {
            ull w0 = pack2(Wsh[g * 80 + gp0]);
            const ulonglong2* rp0 = (const ulonglong2*)(gdn + ((size_t)g * 5 + f0) * 8);
            ulonglong2 q0 = rp0[0], q1 = rp0[1], q2 = rp0[2], q3 = rp0[3];
            acc0[0] = ffma2(w0, q0.x, acc0[0]);
            acc0[1] = ffma2(w0, q0.y, acc0[1]);
            acc0[2] = ffma2(w0, q1.x, acc0[2]);
            acc0[3] = ffma2(w0, q1.y, acc0[3]);
            acc0[4] = ffma2(w0, q2.x, acc0[4]);
            acc0[5] = ffma2(w0, q2.y, acc0[5]);
            acc0[6] = ffma2(w0, q3.x, acc0[6]);
            acc0[7] = ffma2(w0, q3.y, acc0[7]);
            if (has1) {
                ull w1 = pack2(Wsh[g * 80 + gp1]);
                const ulonglong2* rp1 = (const ulonglong2*)(gdn + ((size_t)g * 5 + f1) * 8);
                ulonglong2 p0 = rp1[0], p1 = rp1[1], p2 = rp1[2], p3 = rp1[3];
                acc1[0] = ffma2(w1, p0.x, acc1[0]);
                acc1[1] = ffma2(w1, p0.y, acc1[1]);
                acc1[2] = ffma2(w1, p1.x, acc1[2]);
                acc1[3] = ffma2(w1, p1.y, acc1[3]);
                acc1[4] = ffma2(w1, p2.x, acc1[4]);
                acc1[5] = ffma2(w1, p2.y, acc1[5]);
                acc1[6] = ffma2(w1, p3.x, acc1[6]);
                acc1[7] = ffma2(w1, p3.y, acc1[7]);
            }
        }

        float mx0 = -1e30f;
#pragma unroll
        for (int j = 0; j < 8; j++) {
            float2 q = unpack2(acc0[j]);
            mx0 = fmaxf(mx0, fmaxf(q.x, q.y));
        }
        d_DESC[(size_t)s * 400 + tid] = fmaxf(mx0 + bc[tid], 0.0f);

        if (has1) {
            float mx1 = -1e30f;
#pragma unroll
            for (int j = 0; j < 8; j++) {
                float2 q = unpack2(acc1[j]);
                mx1 = fmaxf(mx1, fmaxf(q.x, q.y));
            }
            d_DESC[(size_t)s * 400 + c1i] = fmaxf(mx1 + bc[c1i], 0.0f);
        }
    }
}

// ---------------------------------------------------------------------------
// k4: grid 64, block 320 = (s_local 0..3, g 0..79). fw staged via smem chunks.
// ---------------------------------------------------------------------------
__global__ __launch_bounds__(320) void k4_fcc(const float* __restrict__ fw,
                                              const float* __restrict__ fb,
                                              float* __restrict__ out)
{
    __shared__ float fwsh[100 * 80];   // 32 KB chunk
    __shared__ float dsh[4 * 400];

    int tid = threadIdx.x;
    int sl  = tid / 80;
    int g   = tid % 80;
    int sb  = blockIdx.x * 4;

    {
        const float4* src = (const float4*)(d_DESC + (size_t)sb * 400);
        float4* dst = (float4*)dsh;
        for (int i = tid; i < 400; i += 320) dst[i] = src[i];
    }

    float acc = 0.0f;
#pragma unroll
    for (int c = 0; c < 4; c++) {
        __syncthreads();
        const float4* src = (const float4*)(fw + (size_t)c * 100 * 80);
        float4* dst = (float4*)fwsh;
        for (int i = tid; i < 2000; i += 320) dst[i] = src[i];
        __syncthreads();

        const float* dr = &dsh[sl * 400 + c * 100];
#pragma unroll 5
        for (int j = 0; j < 100; j++)
            acc = fmaf(dr[j], fwsh[j * 80 + g], acc);
    }

    out[(size_t)(sb + sl) * 80 + g] = fb[g] + acc;
}

// ---------------------------------------------------------------------------
// k5: distances + score + loss. 1024 threads; warp-per-pair, float4 loads,
// shfl reductions. out: [0:20480) desc, [20480] loss, [20481:20609) score
// ---------------------------------------------------------------------------
__global__ __launch_bounds__(1024) void k5_loss(float* __restrict__ out)
{
    __shared__ float sdist[128];
    __shared__ float stats[4];

    int tid  = threadIdx.x;
    int w    = tid >> 5;
    int lane = tid & 31;
    const float* gd = out;

#pragma unroll
    for (int i = 0; i < 4; i++) {
        int p  = w + 32 * i;     // 0..127
        int il = p & 63;
        const float *xa, *xb;
        if (p < 64) { xa = gd + (size_t)(64 + il) * 80;  xb = gd + (size_t)il * 80; }
        else        { xa = gd + (size_t)(128 + il) * 80; xb = gd + (size_t)(192 + il) * 80; }
        float sum = 0.0f;
        if (lane < 20) {
            float4 a4 = ((const float4*)xa)[lane];
            float4 b4 = ((const float4*)xb)[lane];
            float dx = a4.x - b4.x, dy = a4.y - b4.y;
            float dz = a4.z - b4.z, dw = a4.w - b4.w;
            sum = dx * dx + dy * dy + dz * dz + dw * dw;
        }
#pragma unroll
        for (int off = 16; off; off >>= 1)
            sum += __shfl_xor_sync(0xffffffffu, sum, off);
        if (lane == 0) { sdist[p] = sum; out[20481 + p] = sum; }
    }
    __syncthreads();

    if (w == 0) {
        float v1 = fmaxf(sdist[lane], 0.0f);
        float v2 = fmaxf(sdist[lane + 32], 0.0f);
        float sum = v1 + v2;
#pragma unroll
        for (int off = 16; off; off >>= 1)
            sum += __shfl_xor_sync(0xffffffffu, sum, off);
        float m = sum * (1.0f / 64.0f);
        float q = (v1 - m) * (v1 - m) + (v2 - m) * (v2 - m);
#pragma unroll
        for (int off = 16; off; off >>= 1)
            q += __shfl_xor_sync(0xffffffffu, q, off);
        if (lane == 0) { stats[0] = m; stats[1] = q; }
    } else if (w == 1) {
        float v1 = fmaxf(10.0f - sdist[64 + lane], 0.0f);
        float v2 = fmaxf(10.0f - sdist[96 + lane], 0.0f);
        float sum = v1 + v2;
#pragma unroll
        for (int off = 16; off; off >>= 1)
            sum += __shfl_xor_sync(0xffffffffu, sum, off);
        float m = sum * (1.0f / 64.0f);
        float q = (v1 - m) * (v1 - m) + (v2 - m) * (v2 - m);
#pragma unroll
        for (int off = 16; off; off >>= 1)
            q += __shfl_xor_sync(0xffffffffu, q, off);
        if (lane == 0) { stats[2] = m; stats[3] = q; }
    }
    __syncthreads();

    if (tid == 0)
        out[20480] = sqrtf(stats[1] / 63.0f) + sqrtf(stats[3] / 63.0f)
                   + stats[0] + stats[2];
}

// ---------------------------------------------------------------------------
extern "C" void kernel_launch(void* const* d_in, const int* in_sizes, int n_in,
                              void* d_out, int out_size)
{
    const float* input_feat  = (const float*)d_in[0];
    const float* rho_coords  = (const float*)d_in[1];
    const float* theta_coord = (const float*)d_in[2];
    const float* mask        = (const float*)d_in[3];
    const float* mu_rho      = (const float*)d_in[4];
    const float* sigma_rho   = (const float*)d_in[5];
    const float* mu_theta    = (const float*)d_in[6];
    const float* sigma_theta = (const float*)d_in[7];
    const float* W_conv      = (const float*)d_in[8];
    const float* b_conv      = (const float*)d_in[9];
    const float* fcc_w       = (const float*)d_in[10];
    const float* fcc_b       = (const float*)d_in[11];
    float* out = (float*)d_out;

    k123<<<S_N, 256>>>(input_feat, rho_coords, theta_coord, mask,
                       mu_rho, sigma_rho, mu_theta, sigma_theta,
                       W_conv, b_conv);
    k4_fcc<<<S_N / 4, 320>>>(fcc_w, fcc_b, out);
    k5_loss<<<1, 1024>>>(out);
}